// round 13
// baseline (speedup 1.0000x reference)
#include <cuda_runtime.h>
#include <cstdint>

// Table-batched embedding bag, SUM pooling.
// indices: int32 [T*B*L], offsets: int32 [T*B+1], weights: fp32 [T*E, 128],
// hash_size_cumsum: int32 [T+1], out: fp32 [B, T*128]
//
// One warp per bag; lane = one float4 (16B) of the 512B row.
// cp.async.cg into per-warp smem staging, 8 slots (4KB/warp). L=20 fast
// path: 5 straight-line waves of 4 rows, double-buffered over slot halves
// with wait_group 1 -> always >=4 rows in flight per warp.
// launch_bounds(128,12): smem 16KB*12=192<=228, regs<=42 -> 75% occ cap
// (1.5x R11's 46% at the same pipelined duty cycle).

#define EMB_D    128
#define NSLOT    8            // staging slots per warp (two banks of 4)
#define WARPS_PB 4            // 128 threads/block; smem = 4*8*512B = 16KB

__global__ void __launch_bounds__(128, 12) tbe_fwd_kernel(
    const int*   __restrict__ indices,
    const int*   __restrict__ offsets,
    const float* __restrict__ weights,
    const int*   __restrict__ hsc,
    float*       __restrict__ out,
    int batch, int n_tables, int num_bags)
{
    // 4 warps * 8 slots * 32 lanes * 16B = 16 KB
    __shared__ float4 buf[WARPS_PB * NSLOT * 32];

    const int warp_global = (blockIdx.x * blockDim.x + threadIdx.x) >> 5;
    const int lane = threadIdx.x & 31;
    const int wib  = (threadIdx.x >> 5);
    if (warp_global >= num_bags) return;

    float4* mybuf = buf + wib * (NSLOT * 32) + lane;   // slot s at mybuf[s*32]
    const unsigned sbase = (unsigned)__cvta_generic_to_shared(mybuf);

    const int seg   = warp_global;
    const int table = seg / batch;
    const int b     = seg - table * batch;

    const int base  = hsc[table];          // T*E <= 4M, fits int32
    const int start = offsets[seg];
    const int end   = offsets[seg + 1];
    const int len   = end - start;

    const float4* __restrict__ wv = reinterpret_cast<const float4*>(weights);

    float4 a0 = make_float4(0.f, 0.f, 0.f, 0.f);
    float4 a1 = make_float4(0.f, 0.f, 0.f, 0.f);
    float4 a2 = make_float4(0.f, 0.f, 0.f, 0.f);
    float4 a3 = make_float4(0.f, 0.f, 0.f, 0.f);

    // issue CNT rows starting at bag pos KOFF into slots SLOT0..SLOT0+CNT-1
    #define ISSUE(KOFF, SLOT0, CNT)                                            \
        do {                                                                   \
            _Pragma("unroll")                                                  \
            for (int s = 0; s < (CNT); s++) {                                  \
                const unsigned row =                                           \
                    (unsigned)(__shfl_sync(0xffffffffu, myidx, (KOFF) + s) + base); \
                asm volatile("cp.async.cg.shared.global [%0], [%1], 16;\n"     \
                             :: "r"(sbase + ((SLOT0) + s) * 512u),             \
                                "l"(wv + (size_t)row * 32u + lane));           \
            }                                                                  \
            asm volatile("cp.async.commit_group;\n");                          \
        } while (0)

    #define DRAIN4(SLOT0)                                                      \
        do {                                                                   \
            { const float4 v = mybuf[((SLOT0)+0)*32];                          \
              a0.x+=v.x; a0.y+=v.y; a0.z+=v.z; a0.w+=v.w; }                   \
            { const float4 v = mybuf[((SLOT0)+1)*32];                          \
              a1.x+=v.x; a1.y+=v.y; a1.z+=v.z; a1.w+=v.w; }                   \
            { const float4 v = mybuf[((SLOT0)+2)*32];                          \
              a2.x+=v.x; a2.y+=v.y; a2.z+=v.z; a2.w+=v.w; }                   \
            { const float4 v = mybuf[((SLOT0)+3)*32];                          \
              a3.x+=v.x; a3.y+=v.y; a3.z+=v.z; a3.w+=v.w; }                   \
        } while (0)

    #define WAIT1() asm volatile("cp.async.wait_group 1;\n" ::: "memory")
    #define WAIT0() asm volatile("cp.async.wait_group 0;\n" ::: "memory")

    if (len == 20) {
        // fast path: single index load; 5 pipelined waves of 4 over 2 banks
        const int myidx = (lane < 20) ? indices[start + lane] : 0;
        ISSUE(0,  0, 4);            // w0 -> bank A (slots 0..3)
        ISSUE(4,  4, 4);            // w1 -> bank B (slots 4..7)
        WAIT1(); DRAIN4(0);         // w0 done, w1 in flight
        ISSUE(8,  0, 4);            // w2 -> bank A
        WAIT1(); DRAIN4(4);         // w1 done, w2 in flight
        ISSUE(12, 4, 4);            // w3 -> bank B
        WAIT1(); DRAIN4(0);         // w2 done, w3 in flight
        ISSUE(16, 0, 4);            // w4 -> bank A
        WAIT1(); DRAIN4(4);         // w3 done, w4 in flight
        WAIT0(); DRAIN4(0);         // w4 done
    } else {
        // generic fallback: flat issue-8 / wait / drain per group
        for (int chunk = start; chunk < end; chunk += 32) {
            const int cnt = min(32, end - chunk);
            const int myidx = (lane < cnt) ? indices[chunk + lane] : 0;

            for (int k = 0; k < cnt; k += 8) {
                const int ns = min(8, cnt - k);
                #pragma unroll
                for (int s = 0; s < 8; s++) {
                    if (s < ns) {
                        const unsigned row =
                            (unsigned)(__shfl_sync(0xffffffffu, myidx, k + s) + base);
                        asm volatile("cp.async.cg.shared.global [%0], [%1], 16;\n"
                                     :: "r"(sbase + s * 512u),
                                        "l"(wv + (size_t)row * 32u + lane));
                    }
                }
                asm volatile("cp.async.commit_group;\n");
                WAIT0();
                #pragma unroll
                for (int s = 0; s < 8; s += 4) {
                    if (s < ns) { const float4 v = mybuf[s*32];
                        a0.x+=v.x; a0.y+=v.y; a0.z+=v.z; a0.w+=v.w; }
                    if (s+1 < ns) { const float4 v = mybuf[(s+1)*32];
                        a1.x+=v.x; a1.y+=v.y; a1.z+=v.z; a1.w+=v.w; }
                    if (s+2 < ns) { const float4 v = mybuf[(s+2)*32];
                        a2.x+=v.x; a2.y+=v.y; a2.z+=v.z; a2.w+=v.w; }
                    if (s+3 < ns) { const float4 v = mybuf[(s+3)*32];
                        a3.x+=v.x; a3.y+=v.y; a3.z+=v.z; a3.w+=v.w; }
                }
            }
        }
    }
    #undef ISSUE
    #undef DRAIN4
    #undef WAIT1
    #undef WAIT0

    float4 acc;
    acc.x = (a0.x + a1.x) + (a2.x + a3.x);
    acc.y = (a0.y + a1.y) + (a2.y + a3.y);
    acc.z = (a0.z + a1.z) + (a2.z + a3.z);
    acc.w = (a0.w + a1.w) + (a2.w + a3.w);

    float4* o = reinterpret_cast<float4*>(
        out + (size_t)b * ((size_t)n_tables * EMB_D) + (size_t)table * EMB_D);
    o[lane] = acc;
}

extern "C" void kernel_launch(void* const* d_in, const int* in_sizes, int n_in,
                              void* d_out, int out_size)
{
    const int*   indices = (const int*)d_in[0];
    const int*   offsets = (const int*)d_in[1];
    const float* weights = (const float*)d_in[2];
    const int*   hsc     = (const int*)d_in[3];
    float* out = (float*)d_out;

    const int num_bags = in_sizes[1] - 1;   // T*B
    const int n_tables = in_sizes[3] - 1;   // T
    const int batch    = num_bags / n_tables;

    const int blocks = (num_bags + WARPS_PB - 1) / WARPS_PB;

    tbe_fwd_kernel<<<blocks, WARPS_PB * 32>>>(
        indices, offsets, weights, hsc, out, batch, n_tables, num_bags);
}

// round 14
// speedup vs baseline: 1.0123x; 1.0123x over previous
#include <cuda_runtime.h>
#include <cstdint>

// Table-batched embedding bag, SUM pooling.
// indices: int32 [T*B*L], offsets: int32 [T*B+1], weights: fp32 [T*E, 128],
// hash_size_cumsum: int32 [T+1], out: fp32 [B, T*128]
//
// One warp per bag; lane = one float4 (16B) of the 512B row.
// cp.async.cg into per-warp smem staging, 16 slots = 4 banks of 4 rows.
// L=20 fast path: 5 waves of 4, THREE commit-groups kept in flight
// (wait_group 2), so every drain of 4 rows overlaps ~8 rows still loading.
// smem 32KB/block -> 7 blocks/SM; regs free (launch_bounds(128,7)).

#define EMB_D    128
#define NSLOT    16           // 4 banks x 4 slots per warp
#define WARPS_PB 4            // 128 threads/block; smem = 4*16*512B = 32KB

__global__ void __launch_bounds__(128, 7) tbe_fwd_kernel(
    const int*   __restrict__ indices,
    const int*   __restrict__ offsets,
    const float* __restrict__ weights,
    const int*   __restrict__ hsc,
    float*       __restrict__ out,
    int batch, int n_tables, int num_bags)
{
    // 4 warps * 16 slots * 32 lanes * 16B = 32 KB
    __shared__ float4 buf[WARPS_PB * NSLOT * 32];

    const int warp_global = (blockIdx.x * blockDim.x + threadIdx.x) >> 5;
    const int lane = threadIdx.x & 31;
    const int wib  = (threadIdx.x >> 5);
    if (warp_global >= num_bags) return;

    float4* mybuf = buf + wib * (NSLOT * 32) + lane;   // slot s at mybuf[s*32]
    const unsigned sbase = (unsigned)__cvta_generic_to_shared(mybuf);

    const int seg   = warp_global;
    const int table = seg / batch;
    const int b     = seg - table * batch;

    const int base  = hsc[table];          // T*E <= 4M, fits int32
    const int start = offsets[seg];
    const int end   = offsets[seg + 1];
    const int len   = end - start;

    const float4* __restrict__ wv = reinterpret_cast<const float4*>(weights);

    float4 a0 = make_float4(0.f, 0.f, 0.f, 0.f);
    float4 a1 = make_float4(0.f, 0.f, 0.f, 0.f);
    float4 a2 = make_float4(0.f, 0.f, 0.f, 0.f);
    float4 a3 = make_float4(0.f, 0.f, 0.f, 0.f);

    // issue CNT rows starting at bag pos KOFF into slots SLOT0..SLOT0+CNT-1
    #define ISSUE(KOFF, SLOT0, CNT)                                            \
        do {                                                                   \
            _Pragma("unroll")                                                  \
            for (int s = 0; s < (CNT); s++) {                                  \
                const unsigned row =                                           \
                    (unsigned)(__shfl_sync(0xffffffffu, myidx, (KOFF) + s) + base); \
                asm volatile("cp.async.cg.shared.global [%0], [%1], 16;\n"     \
                             :: "r"(sbase + ((SLOT0) + s) * 512u),             \
                                "l"(wv + (size_t)row * 32u + lane));           \
            }                                                                  \
            asm volatile("cp.async.commit_group;\n");                          \
        } while (0)

    #define DRAIN4(SLOT0)                                                      \
        do {                                                                   \
            { const float4 v = mybuf[((SLOT0)+0)*32];                          \
              a0.x+=v.x; a0.y+=v.y; a0.z+=v.z; a0.w+=v.w; }                   \
            { const float4 v = mybuf[((SLOT0)+1)*32];                          \
              a1.x+=v.x; a1.y+=v.y; a1.z+=v.z; a1.w+=v.w; }                   \
            { const float4 v = mybuf[((SLOT0)+2)*32];                          \
              a2.x+=v.x; a2.y+=v.y; a2.z+=v.z; a2.w+=v.w; }                   \
            { const float4 v = mybuf[((SLOT0)+3)*32];                          \
              a3.x+=v.x; a3.y+=v.y; a3.z+=v.z; a3.w+=v.w; }                   \
        } while (0)

    #define WAITG(N) asm volatile("cp.async.wait_group " #N ";\n" ::: "memory")

    if (len == 20) {
        // fast path: single index load; 5 waves of 4, 3 groups in flight
        const int myidx = (lane < 20) ? indices[start + lane] : 0;
        ISSUE(0,   0, 4);           // w0 -> bank A (slots 0..3)
        ISSUE(4,   4, 4);           // w1 -> bank B
        ISSUE(8,   8, 4);           // w2 -> bank C
        WAITG(2); DRAIN4(0);        // w0 done; w1,w2 in flight (8 rows)
        ISSUE(12, 12, 4);           // w3 -> bank D
        WAITG(2); DRAIN4(4);        // w1 done; w2,w3 in flight (8 rows)
        ISSUE(16,  0, 4);           // w4 -> bank A (w0 already drained)
        WAITG(2); DRAIN4(8);        // w2 done; w3,w4 in flight (8 rows)
        WAITG(1); DRAIN4(12);       // w3 done; w4 in flight (4 rows)
        WAITG(0); DRAIN4(0);        // w4 done
    } else {
        // generic fallback: flat issue-8 / wait / drain per group
        for (int chunk = start; chunk < end; chunk += 32) {
            const int cnt = min(32, end - chunk);
            const int myidx = (lane < cnt) ? indices[chunk + lane] : 0;

            for (int k = 0; k < cnt; k += 8) {
                const int ns = min(8, cnt - k);
                #pragma unroll
                for (int s = 0; s < 8; s++) {
                    if (s < ns) {
                        const unsigned row =
                            (unsigned)(__shfl_sync(0xffffffffu, myidx, k + s) + base);
                        asm volatile("cp.async.cg.shared.global [%0], [%1], 16;\n"
                                     :: "r"(sbase + s * 512u),
                                        "l"(wv + (size_t)row * 32u + lane));
                    }
                }
                asm volatile("cp.async.commit_group;\n");
                WAITG(0);
                #pragma unroll
                for (int s = 0; s < 8; s += 4) {
                    if (s < ns) { const float4 v = mybuf[s*32];
                        a0.x+=v.x; a0.y+=v.y; a0.z+=v.z; a0.w+=v.w; }
                    if (s+1 < ns) { const float4 v = mybuf[(s+1)*32];
                        a1.x+=v.x; a1.y+=v.y; a1.z+=v.z; a1.w+=v.w; }
                    if (s+2 < ns) { const float4 v = mybuf[(s+2)*32];
                        a2.x+=v.x; a2.y+=v.y; a2.z+=v.z; a2.w+=v.w; }
                    if (s+3 < ns) { const float4 v = mybuf[(s+3)*32];
                        a3.x+=v.x; a3.y+=v.y; a3.z+=v.z; a3.w+=v.w; }
                }
            }
        }
    }
    #undef ISSUE
    #undef DRAIN4
    #undef WAITG

    float4 acc;
    acc.x = (a0.x + a1.x) + (a2.x + a3.x);
    acc.y = (a0.y + a1.y) + (a2.y + a3.y);
    acc.z = (a0.z + a1.z) + (a2.z + a3.z);
    acc.w = (a0.w + a1.w) + (a2.w + a3.w);

    float4* o = reinterpret_cast<float4*>(
        out + (size_t)b * ((size_t)n_tables * EMB_D) + (size_t)table * EMB_D);
    o[lane] = acc;
}

extern "C" void kernel_launch(void* const* d_in, const int* in_sizes, int n_in,
                              void* d_out, int out_size)
{
    const int*   indices = (const int*)d_in[0];
    const int*   offsets = (const int*)d_in[1];
    const float* weights = (const float*)d_in[2];
    const int*   hsc     = (const int*)d_in[3];
    float* out = (float*)d_out;

    const int num_bags = in_sizes[1] - 1;   // T*B
    const int n_tables = in_sizes[3] - 1;   // T
    const int batch    = num_bags / n_tables;

    const int blocks = (num_bags + WARPS_PB - 1) / WARPS_PB;

    tbe_fwd_kernel<<<blocks, WARPS_PB * 32>>>(
        indices, offsets, weights, hsc, out, batch, n_tables, num_bags);
}